// round 12
// baseline (speedup 1.0000x reference)
#include <cuda_runtime.h>
#include <cuda_fp16.h>
#include <math.h>

#define NN   50000
#define HID  64
#define EE   800000
#define EP   100000
#define LYR  2
#define BN_EPS 1e-5f
#define NB_SCAN 196            // 196 * 256 = 50176 >= NN

// ---------------- scratch ----------------
__device__ float g_x[NN * HID];
__device__ __align__(16) __half g_h[NN * HID];
__device__ float g_agg[NN * HID];
__device__ float g_dis[NN];
__device__ int   g_deg[NN];
__device__ int   g_cnt[NN];
__device__ int   g_row_start[NN + 1];
__device__ int2  g_csr[EE];                      // {src, float_as_int(w)}
__device__ int   g_part[256];
__device__ float g_stats[LYR * 2 * HID];         // per layer: sum, sumsq

// ---------------- init ----------------
__global__ void k_init() {
    int n = blockIdx.x * blockDim.x + threadIdx.x;
    if (n < NN) { g_deg[n] = 1; g_cnt[n] = 0; }
    if (n < LYR * 2 * HID) g_stats[n] = 0.f;
    if (n == 0) g_row_start[NN] = EE;
}

__global__ void k_deg_count(const int* __restrict__ ei) {
    int t = blockIdx.x * blockDim.x + threadIdx.x;
    int e = t * 2;
    if (e < EE) {
        int2 c = *reinterpret_cast<const int2*>(ei + EE + e);
        atomicAdd(&g_deg[c.x], 1);
        atomicAdd(&g_deg[c.y], 1);
    }
}

// ---------------- warp-shuffle scan helpers ----------------
__device__ __forceinline__ int warp_incl_scan(int v, int lane) {
#pragma unroll
    for (int o = 1; o < 32; o <<= 1) {
        int n = __shfl_up_sync(0xffffffffu, v, o);
        if (lane >= o) v += n;
    }
    return v;
}

__device__ __forceinline__ int block_incl_scan(int v, int t, int* wtot) {
    int lane = t & 31, wid = t >> 5;
    int iv = warp_incl_scan(v, lane);
    if (lane == 31) wtot[wid] = iv;
    __syncthreads();
    if (t < 8) {
        int wv = wtot[t];
#pragma unroll
        for (int o = 1; o < 8; o <<= 1) {
            int n = __shfl_up_sync(0xffu, wv, o);
            if (t >= o) wv += n;
        }
        wtot[t] = wv;
    }
    __syncthreads();
    return iv + (wid ? wtot[wid - 1] : 0);
}

// block partial sums of (deg-1), fused with dis = rsqrt(deg)
__global__ void k_scan_part() {
    __shared__ int wtot[8];
    int t = threadIdx.x;
    int lane = t & 31, wid = t >> 5;
    int idx = blockIdx.x * 256 + t;
    int d = (idx < NN) ? g_deg[idx] : 1;
    if (idx < NN) g_dis[idx] = rsqrtf((float)d);
    int v = d - 1;
#pragma unroll
    for (int o = 16; o; o >>= 1) v += __shfl_down_sync(0xffffffffu, v, o);
    if (lane == 0) wtot[wid] = v;
    __syncthreads();
    if (t < 8) {
        int wv = wtot[t];
#pragma unroll
        for (int o = 4; o; o >>= 1) wv += __shfl_down_sync(0xffu, wv, o);
        if (t == 0) g_part[blockIdx.x] = wv;
    }
}

// row_start: scan of 196 partials + per-element block scan
__global__ void k_scan_write() {
    __shared__ int shp[256];
    __shared__ int wtot[8];
    int t = threadIdx.x;
    int pv = (t < NB_SCAN) ? g_part[t] : 0;
    shp[t] = block_incl_scan(pv, t, wtot);
    __syncthreads();
    int boff = shp[blockIdx.x] - g_part[blockIdx.x];   // exclusive prefix of this block

    int idx = blockIdx.x * 256 + t;
    int v = (idx < NN) ? g_deg[idx] - 1 : 0;
    __syncthreads();
    int incl = block_incl_scan(v, t, wtot);
    if (idx < NN) g_row_start[idx] = boff + incl - v;
}

__global__ void k_csr_fill(const int* __restrict__ ei) {
    int t = blockIdx.x * blockDim.x + threadIdx.x;
    int e = t * 2;
    if (e >= EE) return;
    int2 r = *reinterpret_cast<const int2*>(ei + e);
    int2 c = *reinterpret_cast<const int2*>(ei + EE + e);
    {
        int pos = g_row_start[c.x] + atomicAdd(&g_cnt[c.x], 1);
        float w = __ldg(g_dis + r.x) * __ldg(g_dis + c.x);
        g_csr[pos] = make_int2(r.x, __float_as_int(w));
    }
    {
        int pos = g_row_start[c.y] + atomicAdd(&g_cnt[c.y], 1);
        float w = __ldg(g_dis + r.y) * __ldg(g_dis + c.y);
        g_csr[pos] = make_int2(r.y, __float_as_int(w));
    }
}

// ============ GEMM helpers: 128x64 block tile, 8x4 thread tile ============
__device__ __forceinline__ void mm_accum8(const float* Xs, const float* Ws,
                                          int n0, int c0, float4 acc[8]) {
#pragma unroll
    for (int k = 0; k < 64; k += 4) {
        float4 wv0 = *reinterpret_cast<const float4*>(Ws + (k + 0) * 64 + c0);
        float4 wv1 = *reinterpret_cast<const float4*>(Ws + (k + 1) * 64 + c0);
        float4 wv2 = *reinterpret_cast<const float4*>(Ws + (k + 2) * 64 + c0);
        float4 wv3 = *reinterpret_cast<const float4*>(Ws + (k + 3) * 64 + c0);
#pragma unroll
        for (int i = 0; i < 8; i++) {
            float4 xv = *reinterpret_cast<const float4*>(Xs + (n0 + i) * 64 + k);
            acc[i].x += xv.x * wv0.x + xv.y * wv1.x + xv.z * wv2.x + xv.w * wv3.x;
            acc[i].y += xv.x * wv0.y + xv.y * wv1.y + xv.z * wv2.y + xv.w * wv3.y;
            acc[i].z += xv.x * wv0.z + xv.y * wv1.z + xv.z * wv2.z + xv.w * wv3.z;
            acc[i].w += xv.x * wv0.w + xv.y * wv1.w + xv.z * wv2.w + xv.w * wv3.w;
        }
    }
}

__device__ __forceinline__ void store_h_fp16(const float4 acc[8], int base, int n0, int c0) {
#pragma unroll
    for (int i = 0; i < 8; i++) {
        int gn = base + n0 + i;
        if (gn < NN) {
            __half2* dst = reinterpret_cast<__half2*>(g_h + gn * 64 + c0);
            dst[0] = __floats2half2_rn(acc[i].x, acc[i].y);
            dst[1] = __floats2half2_rn(acc[i].z, acc[i].w);
        }
    }
}

// uint2 (4 x fp16) -> float4
__device__ __forceinline__ float4 h4_to_f4(uint2 v) {
    __half2 a = *reinterpret_cast<__half2*>(&v.x);
    __half2 b = *reinterpret_cast<__half2*>(&v.y);
    float2 fa = __half22float2(a);
    float2 fb = __half22float2(b);
    return make_float4(fa.x, fa.y, fb.x, fb.y);
}

// ---------------- input projection: x = [id|n2v] @ W + b ----------------
__global__ __launch_bounds__(256) void k_proj(const float* __restrict__ id_emb,
                                              const float* __restrict__ n2v_emb,
                                              const float* __restrict__ W,
                                              const float* __restrict__ b) {
    __shared__ float Xs[128 * 64];
    __shared__ float Ws[64 * 64];
    int tid = threadIdx.x;
    int base = blockIdx.x * 128;
    int c0 = (tid & 15) * 4, n0 = (tid >> 4) * 8;

    float4 acc[8];
#pragma unroll
    for (int i = 0; i < 8; i++) acc[i] = make_float4(0.f, 0.f, 0.f, 0.f);

#pragma unroll
    for (int chunk = 0; chunk < 2; chunk++) {
        const float* src = chunk ? n2v_emb : id_emb;
        for (int j = tid; j < 128 * 16; j += 256) {
            int gn = base + (j >> 4);
            float4 v = make_float4(0.f, 0.f, 0.f, 0.f);
            if (gn < NN) v = *reinterpret_cast<const float4*>(src + gn * 64 + (j & 15) * 4);
            *reinterpret_cast<float4*>(Xs + j * 4) = v;
        }
        const float* Wsrc = W + chunk * 64 * 64;
        for (int j = tid; j < 1024; j += 256)
            *reinterpret_cast<float4*>(Ws + j * 4) =
                *reinterpret_cast<const float4*>(Wsrc + j * 4);
        __syncthreads();
        mm_accum8(Xs, Ws, n0, c0, acc);
        __syncthreads();
    }

    float4 b4 = *reinterpret_cast<const float4*>(b + c0);
#pragma unroll
    for (int i = 0; i < 8; i++) {
        int gn = base + n0 + i;
        if (gn < NN) {
            float4 o = make_float4(acc[i].x + b4.x, acc[i].y + b4.y,
                                   acc[i].z + b4.z, acc[i].w + b4.w);
            *reinterpret_cast<float4*>(g_x + gn * 64 + c0) = o;
        }
    }
}

// ---------------- conv GEMM: h = x @ W, written fp16 ----------------
__global__ __launch_bounds__(256) void k_conv(const float* __restrict__ W) {
    __shared__ float Xs[128 * 64];
    __shared__ float Ws[64 * 64];
    int tid = threadIdx.x;
    int base = blockIdx.x * 128;
    int c0 = (tid & 15) * 4, n0 = (tid >> 4) * 8;

    for (int j = tid; j < 128 * 16; j += 256) {
        int gn = base + (j >> 4);
        float4 v = make_float4(0.f, 0.f, 0.f, 0.f);
        if (gn < NN) v = *reinterpret_cast<const float4*>(g_x + gn * 64 + (j & 15) * 4);
        *reinterpret_cast<float4*>(Xs + j * 4) = v;
    }
    for (int j = tid; j < 1024; j += 256)
        *reinterpret_cast<float4*>(Ws + j * 4) =
            *reinterpret_cast<const float4*>(W + j * 4);
    __syncthreads();

    float4 acc[8];
#pragma unroll
    for (int i = 0; i < 8; i++) acc[i] = make_float4(0.f, 0.f, 0.f, 0.f);
    mm_accum8(Xs, Ws, n0, c0, acc);
    store_h_fp16(acc, base, n0, c0);
}

// ---------------- fused: xnew = x + relu(BN0(agg));  h1 = xnew @ Wc1 (fp16) -----
__global__ __launch_bounds__(256) void k_bn_conv1(const float* __restrict__ Wc,
                                                  const float* __restrict__ gamma,
                                                  const float* __restrict__ beta) {
    __shared__ float Xs[128 * 64];
    __shared__ float Ws[64 * 64];
    int tid = threadIdx.x;
    int base = blockIdx.x * 128;
    int cload = (tid & 15) * 4;

    float sc[4], sf[4];
#pragma unroll
    for (int i = 0; i < 4; i++) {
        int c = cload + i;
        float mu  = __ldg(g_stats + c) * (1.0f / NN);
        float var = __ldg(g_stats + 64 + c) * (1.0f / NN) - mu * mu;
        float inv = rsqrtf(var + BN_EPS);
        float gm  = __ldg(gamma + c);
        sc[i] = gm * inv;
        sf[i] = __ldg(beta + c) - mu * inv * gm;
    }

    for (int j = tid; j < 128 * 16; j += 256) {
        int gn = base + (j >> 4);
        float4 xn = make_float4(0.f, 0.f, 0.f, 0.f);
        if (gn < NN) {
            float4 a = *reinterpret_cast<const float4*>(g_agg + gn * 64 + cload);
            float4 x = *reinterpret_cast<const float4*>(g_x   + gn * 64 + cload);
            xn.x = x.x + fmaxf(a.x * sc[0] + sf[0], 0.f);
            xn.y = x.y + fmaxf(a.y * sc[1] + sf[1], 0.f);
            xn.z = x.z + fmaxf(a.z * sc[2] + sf[2], 0.f);
            xn.w = x.w + fmaxf(a.w * sc[3] + sf[3], 0.f);
            *reinterpret_cast<float4*>(g_x + gn * 64 + cload) = xn;
        }
        *reinterpret_cast<float4*>(Xs + j * 4) = xn;
    }
    for (int j = tid; j < 1024; j += 256)
        *reinterpret_cast<float4*>(Ws + j * 4) =
            *reinterpret_cast<const float4*>(Wc + j * 4);
    __syncthreads();

    int c0 = (tid & 15) * 4, n0 = (tid >> 4) * 8;
    float4 acc[8];
#pragma unroll
    for (int i = 0; i < 8; i++) acc[i] = make_float4(0.f, 0.f, 0.f, 0.f);
    mm_accum8(Xs, Ws, n0, c0, acc);
    store_h_fp16(acc, base, n0, c0);
}

// ---------------- CSR gather v2: warp per node, half-warp per edge --------------
// Lanes 0-15 process even edges, lanes 16-31 odd edges; each lane owns 4 columns
// (8B uint2 loads). One shfl_xor(16) merges the halves at the end.
__global__ __launch_bounds__(256) void k_gather(const float* __restrict__ conv_b,
                                                int layer) {
    __shared__ float s_stats[128];
    int tid = threadIdx.x;
    if (tid < 128) s_stats[tid] = 0.f;
    __syncthreads();

    int warp = (blockIdx.x * blockDim.x + tid) >> 5;
    int lane = tid & 31;
    int half = lane >> 4, l16 = lane & 15;
    float4 acc = make_float4(0.f, 0.f, 0.f, 0.f);

    if (warp < NN) {
        int n = warp;
        int s0 = __ldg(g_row_start + n);
        int s1 = __ldg(g_row_start + n + 1);
        float d = __ldg(g_dis + n);
        float sl = d * d;

        if (half == 0) {
            uint2 hv = __ldg(reinterpret_cast<const uint2*>(g_h + n * 64) + l16);
            float4 h4 = h4_to_f4(hv);
            float4 b4 = *reinterpret_cast<const float4*>(conv_b + l16 * 4);
            acc.x = b4.x + sl * h4.x;
            acc.y = b4.y + sl * h4.y;
            acc.z = b4.z + sl * h4.z;
            acc.w = b4.w + sl * h4.w;
        }

        int e = s0;
        // 2 pairs per iteration (4 edges) for MLP
        for (; e + 3 < s1; e += 4) {
            int2 m0 = __ldg(g_csr + e + half);
            int2 m1 = __ldg(g_csr + e + 2 + half);
            uint2 v0 = __ldg(reinterpret_cast<const uint2*>(g_h + m0.x * 64) + l16);
            uint2 v1 = __ldg(reinterpret_cast<const uint2*>(g_h + m1.x * 64) + l16);
            float w0 = __int_as_float(m0.y);
            float w1 = __int_as_float(m1.y);
            float4 h0 = h4_to_f4(v0);
            float4 h1 = h4_to_f4(v1);
            acc.x += w0 * h0.x + w1 * h1.x;
            acc.y += w0 * h0.y + w1 * h1.y;
            acc.z += w0 * h0.z + w1 * h1.z;
            acc.w += w0 * h0.w + w1 * h1.w;
        }
        for (; e + 1 < s1; e += 2) {
            int2 m = __ldg(g_csr + e + half);
            uint2 v = __ldg(reinterpret_cast<const uint2*>(g_h + m.x * 64) + l16);
            float w = __int_as_float(m.y);
            float4 h4 = h4_to_f4(v);
            acc.x += w * h4.x;
            acc.y += w * h4.y;
            acc.z += w * h4.z;
            acc.w += w * h4.w;
        }
        if (e < s1) {                               // odd tail: upper half w=0
            int2 m = __ldg(g_csr + e);
            uint2 v = __ldg(reinterpret_cast<const uint2*>(g_h + m.x * 64) + l16);
            float w = half ? 0.f : __int_as_float(m.y);
            float4 h4 = h4_to_f4(v);
            acc.x += w * h4.x;
            acc.y += w * h4.y;
            acc.z += w * h4.z;
            acc.w += w * h4.w;
        }

        // merge the two half-warp accumulators
        acc.x += __shfl_xor_sync(0xffffffffu, acc.x, 16);
        acc.y += __shfl_xor_sync(0xffffffffu, acc.y, 16);
        acc.z += __shfl_xor_sync(0xffffffffu, acc.z, 16);
        acc.w += __shfl_xor_sync(0xffffffffu, acc.w, 16);

        if (half == 0)
            *reinterpret_cast<float4*>(g_agg + n * 64 + l16 * 4) = acc;
    }

    if (half == 0 && warp < NN) {
        int c0 = l16 * 4;
        atomicAdd(&s_stats[c0 + 0], acc.x);
        atomicAdd(&s_stats[c0 + 1], acc.y);
        atomicAdd(&s_stats[c0 + 2], acc.z);
        atomicAdd(&s_stats[c0 + 3], acc.w);
        atomicAdd(&s_stats[64 + c0 + 0], acc.x * acc.x);
        atomicAdd(&s_stats[64 + c0 + 1], acc.y * acc.y);
        atomicAdd(&s_stats[64 + c0 + 2], acc.z * acc.z);
        atomicAdd(&s_stats[64 + c0 + 3], acc.w * acc.w);
    }
    __syncthreads();
    if (tid < 128) atomicAdd(&g_stats[layer * 128 + tid], s_stats[tid]);
}

// ---------------- BN finalize + apply + residual relu (layer 1 only) ------------
__global__ void k_bn_apply(const float* __restrict__ gamma,
                           const float* __restrict__ beta, int layer) {
    __shared__ float sc[64], sf[64];
    int tid = threadIdx.x;
    if (tid < 64) {
        float mu  = g_stats[layer * 128 + tid] * (1.0f / NN);
        float var = g_stats[layer * 128 + 64 + tid] * (1.0f / NN) - mu * mu;
        float inv = rsqrtf(var + BN_EPS);
        float gm  = gamma[tid];
        sc[tid] = gm * inv;
        sf[tid] = beta[tid] - mu * inv * gm;
    }
    __syncthreads();
    int i = blockIdx.x * blockDim.x + tid;
    if (i < NN * 16) {
        int c0 = (i & 15) * 4;
        float4 v = reinterpret_cast<const float4*>(g_agg)[i];
        float4 x = reinterpret_cast<const float4*>(g_x)[i];
        x.x += fmaxf(v.x * sc[c0 + 0] + sf[c0 + 0], 0.f);
        x.y += fmaxf(v.y * sc[c0 + 1] + sf[c0 + 1], 0.f);
        x.z += fmaxf(v.z * sc[c0 + 2] + sf[c0 + 2], 0.f);
        x.w += fmaxf(v.w * sc[c0 + 3] + sf[c0 + 3], 0.f);
        reinterpret_cast<float4*>(g_x)[i] = x;
    }
}

// ---------------- link decoder ----------------
__global__ void k_decode(const int* __restrict__ pe, float* __restrict__ out) {
    int w = (blockIdx.x * blockDim.x + threadIdx.x) >> 5;
    int lane = threadIdx.x & 31;
    if (w >= EP) return;
    int a = __ldg(pe + 2 * w);
    int b = __ldg(pe + 2 * w + 1);
    float2 za = __ldg(reinterpret_cast<const float2*>(g_x + a * 64) + lane);
    float2 zb = __ldg(reinterpret_cast<const float2*>(g_x + b * 64) + lane);
    float s = za.x * zb.x + za.y * zb.y;
#pragma unroll
    for (int o = 16; o; o >>= 1) s += __shfl_xor_sync(0xffffffffu, s, o);
    if (lane == 0) out[w] = s;
}

// ---------------- launch: fork-join — CSR build || (proj -> conv0) ----------------
extern "C" void kernel_launch(void* const* d_in, const int* in_sizes, int n_in,
                              void* d_out, int out_size) {
    const int*   edge_index = (const int*)d_in[0];
    const int*   pred_edge  = (const int*)d_in[1];
    const float* id_emb     = (const float*)d_in[2];
    const float* n2v_emb    = (const float*)d_in[3];
    const float* proj_w     = (const float*)d_in[4];
    const float* proj_b     = (const float*)d_in[5];
    const float* conv_w     = (const float*)d_in[6];
    const float* conv_b     = (const float*)d_in[7];
    const float* bn_gamma   = (const float*)d_in[8];
    const float* bn_beta    = (const float*)d_in[9];
    float*       out        = (float*)d_out;

    static cudaStream_t s_aux = 0;
    static cudaEvent_t ev_fork = 0, ev_join = 0;
    if (!s_aux) {
        cudaStreamCreateWithFlags(&s_aux, cudaStreamNonBlocking);
        cudaEventCreateWithFlags(&ev_fork, cudaEventDisableTiming);
        cudaEventCreateWithFlags(&ev_join, cudaEventDisableTiming);
    }

    const int TB = 256;
    const int GBLK = (NN + 127) / 128;

    // fork: aux stream runs proj -> conv0 (touches only g_x/g_h)
    cudaEventRecord(ev_fork, 0);
    cudaStreamWaitEvent(s_aux, ev_fork, 0);
    k_proj<<<GBLK, TB, 0, s_aux>>>(id_emb, n2v_emb, proj_w, proj_b);
    k_conv<<<GBLK, TB, 0, s_aux>>>(conv_w);
    cudaEventRecord(ev_join, s_aux);

    // main stream: CSR build (touches only deg/dis/csr/stats)
    k_init      <<<(NN + TB - 1) / TB, TB>>>();
    k_deg_count <<<(EE / 2 + TB - 1) / TB, TB>>>(edge_index);
    k_scan_part <<<NB_SCAN, TB>>>();
    k_scan_write<<<NB_SCAN, TB>>>();
    k_csr_fill  <<<(EE / 2 + TB - 1) / TB, TB>>>(edge_index);

    // join: gather0 needs both CSR and h0
    cudaStreamWaitEvent(0, ev_join, 0);

    k_gather  <<<(NN * 32 + TB - 1) / TB, TB>>>(conv_b, 0);
    k_bn_conv1<<<GBLK, TB>>>(conv_w + HID * HID, bn_gamma, bn_beta);   // fused BN0+conv1
    k_gather  <<<(NN * 32 + TB - 1) / TB, TB>>>(conv_b + HID, 1);
    k_bn_apply<<<(NN * 16 + TB - 1) / TB, TB>>>(bn_gamma + HID, bn_beta + HID, 1);

    k_decode<<<(EP * 32 + TB - 1) / TB, TB>>>(pred_edge, out);
}

// round 15
// speedup vs baseline: 1.0367x; 1.0367x over previous
#include <cuda_runtime.h>
#include <cuda_fp16.h>
#include <stdint.h>
#include <math.h>

#define NN   50000
#define HID  64
#define EE   800000
#define EP   100000
#define LYR  2
#define BN_EPS 1e-5f
#define NB_SCAN 196            // 196 * 256 = 50176 >= NN
#define XSTR 68                // smem row stride (floats): 16B-aligned, conflict-free A frags

// ---------------- scratch ----------------
__device__ float g_x[NN * HID];
__device__ __align__(16) __half g_h[NN * HID];
__device__ float g_agg[NN * HID];
__device__ float g_dis[NN];
__device__ int   g_deg[NN];
__device__ int   g_cnt[NN];
__device__ int   g_row_start[NN + 1];
__device__ int2  g_csr[EE];                      // {src, float_as_int(w)}
__device__ int   g_part[256];
__device__ float g_stats[LYR * 2 * HID];         // per layer: sum, sumsq

// ---------------- init ----------------
__global__ void k_init() {
    int n = blockIdx.x * blockDim.x + threadIdx.x;
    if (n < NN) { g_deg[n] = 1; g_cnt[n] = 0; }
    if (n < LYR * 2 * HID) g_stats[n] = 0.f;
    if (n == 0) g_row_start[NN] = EE;
}

__global__ void k_deg_count(const int* __restrict__ ei) {
    int t = blockIdx.x * blockDim.x + threadIdx.x;
    int e = t * 2;
    if (e < EE) {
        int2 c = *reinterpret_cast<const int2*>(ei + EE + e);
        atomicAdd(&g_deg[c.x], 1);
        atomicAdd(&g_deg[c.y], 1);
    }
}

// ---------------- warp-shuffle scan helpers ----------------
__device__ __forceinline__ int warp_incl_scan(int v, int lane) {
#pragma unroll
    for (int o = 1; o < 32; o <<= 1) {
        int n = __shfl_up_sync(0xffffffffu, v, o);
        if (lane >= o) v += n;
    }
    return v;
}

__device__ __forceinline__ int block_incl_scan(int v, int t, int* wtot) {
    int lane = t & 31, wid = t >> 5;
    int iv = warp_incl_scan(v, lane);
    if (lane == 31) wtot[wid] = iv;
    __syncthreads();
    if (t < 8) {
        int wv = wtot[t];
#pragma unroll
        for (int o = 1; o < 8; o <<= 1) {
            int n = __shfl_up_sync(0xffu, wv, o);
            if (t >= o) wv += n;
        }
        wtot[t] = wv;
    }
    __syncthreads();
    return iv + (wid ? wtot[wid - 1] : 0);
}

__global__ void k_scan_part() {
    __shared__ int wtot[8];
    int t = threadIdx.x;
    int lane = t & 31, wid = t >> 5;
    int idx = blockIdx.x * 256 + t;
    int d = (idx < NN) ? g_deg[idx] : 1;
    if (idx < NN) g_dis[idx] = rsqrtf((float)d);
    int v = d - 1;
#pragma unroll
    for (int o = 16; o; o >>= 1) v += __shfl_down_sync(0xffffffffu, v, o);
    if (lane == 0) wtot[wid] = v;
    __syncthreads();
    if (t < 8) {
        int wv = wtot[t];
#pragma unroll
        for (int o = 4; o; o >>= 1) wv += __shfl_down_sync(0xffu, wv, o);
        if (t == 0) g_part[blockIdx.x] = wv;
    }
}

__global__ void k_scan_write() {
    __shared__ int shp[256];
    __shared__ int wtot[8];
    int t = threadIdx.x;
    int pv = (t < NB_SCAN) ? g_part[t] : 0;
    shp[t] = block_incl_scan(pv, t, wtot);
    __syncthreads();
    int boff = shp[blockIdx.x] - g_part[blockIdx.x];

    int idx = blockIdx.x * 256 + t;
    int v = (idx < NN) ? g_deg[idx] - 1 : 0;
    __syncthreads();
    int incl = block_incl_scan(v, t, wtot);
    if (idx < NN) g_row_start[idx] = boff + incl - v;
}

__global__ void k_csr_fill(const int* __restrict__ ei) {
    int t = blockIdx.x * blockDim.x + threadIdx.x;
    int e = t * 2;
    if (e >= EE) return;
    int2 r = *reinterpret_cast<const int2*>(ei + e);
    int2 c = *reinterpret_cast<const int2*>(ei + EE + e);
    {
        int pos = g_row_start[c.x] + atomicAdd(&g_cnt[c.x], 1);
        float w = __ldg(g_dis + r.x) * __ldg(g_dis + c.x);
        g_csr[pos] = make_int2(r.x, __float_as_int(w));
    }
    {
        int pos = g_row_start[c.y] + atomicAdd(&g_cnt[c.y], 1);
        float w = __ldg(g_dis + r.y) * __ldg(g_dis + c.y);
        g_csr[pos] = make_int2(r.y, __float_as_int(w));
    }
}

// ============ tf32 MMA GEMM: 64x64 block tile, 8 warps ============
__device__ __forceinline__ float4 f4_tf32(float4 v) {
    uint32_t a, b, c, d;
    asm("cvt.rna.tf32.f32 %0, %1;" : "=r"(a) : "f"(v.x));
    asm("cvt.rna.tf32.f32 %0, %1;" : "=r"(b) : "f"(v.y));
    asm("cvt.rna.tf32.f32 %0, %1;" : "=r"(c) : "f"(v.z));
    asm("cvt.rna.tf32.f32 %0, %1;" : "=r"(d) : "f"(v.w));
    return make_float4(__uint_as_float(a), __uint_as_float(b),
                       __uint_as_float(c), __uint_as_float(d));
}

// warp computes rows [rowBase,rowBase+16) x cols [colBase,colBase+32); c[nt][4]
__device__ __forceinline__ void mma_warp(const float* Xs, const float* Ws,
                                         int rowBase, int colBase, int lane,
                                         float c[4][4]) {
    int g = lane >> 2, q = lane & 3;
#pragma unroll
    for (int k0 = 0; k0 < 64; k0 += 8) {
        uint32_t a0 = __float_as_uint(Xs[(rowBase + g) * XSTR + k0 + q]);
        uint32_t a1 = __float_as_uint(Xs[(rowBase + g + 8) * XSTR + k0 + q]);
        uint32_t a2 = __float_as_uint(Xs[(rowBase + g) * XSTR + k0 + q + 4]);
        uint32_t a3 = __float_as_uint(Xs[(rowBase + g + 8) * XSTR + k0 + q + 4]);
#pragma unroll
        for (int nt = 0; nt < 4; nt++) {
            int n0 = colBase + nt * 8;
            uint32_t b0 = __float_as_uint(Ws[(k0 + q) * XSTR + n0 + g]);
            uint32_t b1 = __float_as_uint(Ws[(k0 + q + 4) * XSTR + n0 + g]);
            asm("mma.sync.aligned.m16n8k8.row.col.f32.tf32.tf32.f32 "
                "{%0,%1,%2,%3}, {%4,%5,%6,%7}, {%8,%9}, {%0,%1,%2,%3};"
                : "+f"(c[nt][0]), "+f"(c[nt][1]), "+f"(c[nt][2]), "+f"(c[nt][3])
                : "r"(a0), "r"(a1), "r"(a2), "r"(a3), "r"(b0), "r"(b1));
        }
    }
}

// ---------------- input projection: x = [id|n2v] @ W + b (tf32 MMA) -------------
__global__ __launch_bounds__(256) void k_proj(const float* __restrict__ id_emb,
                                              const float* __restrict__ n2v_emb,
                                              const float* __restrict__ W,
                                              const float* __restrict__ b) {
    __shared__ float Xs[64 * XSTR];
    __shared__ float Ws[64 * XSTR];
    int tid = threadIdx.x;
    int base = blockIdx.x * 64;
    int wid = tid >> 5, lane = tid & 31;
    int rowBase = (wid & 3) * 16, colBase = (wid >> 2) * 32;

    float c[4][4];
#pragma unroll
    for (int nt = 0; nt < 4; nt++)
#pragma unroll
        for (int i = 0; i < 4; i++) c[nt][i] = 0.f;

#pragma unroll
    for (int chunk = 0; chunk < 2; chunk++) {
        const float* src = chunk ? n2v_emb : id_emb;
        for (int j = tid; j < 64 * 16; j += 256) {
            int gn = base + (j >> 4);
            float4 v = make_float4(0.f, 0.f, 0.f, 0.f);
            if (gn < NN) v = *reinterpret_cast<const float4*>(src + gn * 64 + (j & 15) * 4);
            *reinterpret_cast<float4*>(Xs + (j >> 4) * XSTR + (j & 15) * 4) = f4_tf32(v);
        }
        const float* Wsrc = W + chunk * 64 * 64;
        for (int j = tid; j < 64 * 16; j += 256) {
            float4 v = *reinterpret_cast<const float4*>(Wsrc + (j >> 4) * 64 + (j & 15) * 4);
            *reinterpret_cast<float4*>(Ws + (j >> 4) * XSTR + (j & 15) * 4) = f4_tf32(v);
        }
        __syncthreads();
        mma_warp(Xs, Ws, rowBase, colBase, lane, c);
        __syncthreads();
    }

    int g = lane >> 2, q = lane & 3;
    int r0 = base + rowBase + g, r1 = r0 + 8;
#pragma unroll
    for (int nt = 0; nt < 4; nt++) {
        int col = colBase + nt * 8 + q * 2;
        float2 b2 = *reinterpret_cast<const float2*>(b + col);
        if (r0 < NN)
            *reinterpret_cast<float2*>(g_x + r0 * 64 + col) =
                make_float2(c[nt][0] + b2.x, c[nt][1] + b2.y);
        if (r1 < NN)
            *reinterpret_cast<float2*>(g_x + r1 * 64 + col) =
                make_float2(c[nt][2] + b2.x, c[nt][3] + b2.y);
    }
}

// ---------------- conv GEMM: h = x @ W (tf32 MMA), written fp16 -----------------
__global__ __launch_bounds__(256) void k_conv(const float* __restrict__ W) {
    __shared__ float Xs[64 * XSTR];
    __shared__ float Ws[64 * XSTR];
    int tid = threadIdx.x;
    int base = blockIdx.x * 64;
    int wid = tid >> 5, lane = tid & 31;
    int rowBase = (wid & 3) * 16, colBase = (wid >> 2) * 32;

    for (int j = tid; j < 64 * 16; j += 256) {
        int gn = base + (j >> 4);
        float4 v = make_float4(0.f, 0.f, 0.f, 0.f);
        if (gn < NN) v = *reinterpret_cast<const float4*>(g_x + gn * 64 + (j & 15) * 4);
        *reinterpret_cast<float4*>(Xs + (j >> 4) * XSTR + (j & 15) * 4) = f4_tf32(v);
    }
    for (int j = tid; j < 64 * 16; j += 256) {
        float4 v = *reinterpret_cast<const float4*>(W + (j >> 4) * 64 + (j & 15) * 4);
        *reinterpret_cast<float4*>(Ws + (j >> 4) * XSTR + (j & 15) * 4) = f4_tf32(v);
    }
    __syncthreads();

    float c[4][4];
#pragma unroll
    for (int nt = 0; nt < 4; nt++)
#pragma unroll
        for (int i = 0; i < 4; i++) c[nt][i] = 0.f;
    mma_warp(Xs, Ws, rowBase, colBase, lane, c);

    int g = lane >> 2, q = lane & 3;
    int r0 = base + rowBase + g, r1 = r0 + 8;
#pragma unroll
    for (int nt = 0; nt < 4; nt++) {
        int col = colBase + nt * 8 + q * 2;
        if (r0 < NN)
            *reinterpret_cast<__half2*>(g_h + r0 * 64 + col) =
                __floats2half2_rn(c[nt][0], c[nt][1]);
        if (r1 < NN)
            *reinterpret_cast<__half2*>(g_h + r1 * 64 + col) =
                __floats2half2_rn(c[nt][2], c[nt][3]);
    }
}

// ---------------- fused: xnew = x + relu(BN0(agg));  h1 = xnew @ Wc1 ------------
__global__ __launch_bounds__(256) void k_bn_conv1(const float* __restrict__ Wc,
                                                  const float* __restrict__ gamma,
                                                  const float* __restrict__ beta) {
    __shared__ float Xs[64 * XSTR];
    __shared__ float Ws[64 * XSTR];
    int tid = threadIdx.x;
    int base = blockIdx.x * 64;
    int wid = tid >> 5, lane = tid & 31;
    int rowBase = (wid & 3) * 16, colBase = (wid >> 2) * 32;
    int cload = (tid & 15) * 4;

    float sc[4], sf[4];
#pragma unroll
    for (int i = 0; i < 4; i++) {
        int cc = cload + i;
        float mu  = __ldg(g_stats + cc) * (1.0f / NN);
        float var = __ldg(g_stats + 64 + cc) * (1.0f / NN) - mu * mu;
        float inv = rsqrtf(var + BN_EPS);
        float gm  = __ldg(gamma + cc);
        sc[i] = gm * inv;
        sf[i] = __ldg(beta + cc) - mu * inv * gm;
    }

    for (int j = tid; j < 64 * 16; j += 256) {
        int gn = base + (j >> 4);
        float4 xn = make_float4(0.f, 0.f, 0.f, 0.f);
        if (gn < NN) {
            float4 a = *reinterpret_cast<const float4*>(g_agg + gn * 64 + cload);
            float4 x = *reinterpret_cast<const float4*>(g_x   + gn * 64 + cload);
            xn.x = x.x + fmaxf(a.x * sc[0] + sf[0], 0.f);
            xn.y = x.y + fmaxf(a.y * sc[1] + sf[1], 0.f);
            xn.z = x.z + fmaxf(a.z * sc[2] + sf[2], 0.f);
            xn.w = x.w + fmaxf(a.w * sc[3] + sf[3], 0.f);
            *reinterpret_cast<float4*>(g_x + gn * 64 + cload) = xn;
        }
        *reinterpret_cast<float4*>(Xs + (j >> 4) * XSTR + cload) = f4_tf32(xn);
    }
    for (int j = tid; j < 64 * 16; j += 256) {
        float4 v = *reinterpret_cast<const float4*>(Wc + (j >> 4) * 64 + (j & 15) * 4);
        *reinterpret_cast<float4*>(Ws + (j >> 4) * XSTR + (j & 15) * 4) = f4_tf32(v);
    }
    __syncthreads();

    float c[4][4];
#pragma unroll
    for (int nt = 0; nt < 4; nt++)
#pragma unroll
        for (int i = 0; i < 4; i++) c[nt][i] = 0.f;
    mma_warp(Xs, Ws, rowBase, colBase, lane, c);

    int g = lane >> 2, q = lane & 3;
    int r0 = base + rowBase + g, r1 = r0 + 8;
#pragma unroll
    for (int nt = 0; nt < 4; nt++) {
        int col = colBase + nt * 8 + q * 2;
        if (r0 < NN)
            *reinterpret_cast<__half2*>(g_h + r0 * 64 + col) =
                __floats2half2_rn(c[nt][0], c[nt][1]);
        if (r1 < NN)
            *reinterpret_cast<__half2*>(g_h + r1 * 64 + col) =
                __floats2half2_rn(c[nt][2], c[nt][3]);
    }
}

// ---------------- CSR gather (fp16 source): warp per node + fused BN stats ------
__global__ __launch_bounds__(256) void k_gather(const float* __restrict__ conv_b,
                                                int layer) {
    __shared__ float s_stats[128];
    int tid = threadIdx.x;
    if (tid < 128) s_stats[tid] = 0.f;
    __syncthreads();

    int warp = (blockIdx.x * blockDim.x + tid) >> 5;
    int lane = tid & 31;
    float2 acc = make_float2(0.f, 0.f);

    if (warp < NN) {
        int n = warp;
        int s0 = __ldg(g_row_start + n);
        int s1 = __ldg(g_row_start + n + 1);
        float d = __ldg(g_dis + n);
        float sl = d * d;
        float2 h2 = __half22float2(
            __ldg(reinterpret_cast<const __half2*>(g_h + n * 64) + lane));
        float2 b2 = *reinterpret_cast<const float2*>(conv_b + lane * 2);
        acc.x = b2.x + h2.x * sl;
        acc.y = b2.y + h2.y * sl;

        int e = s0;
        for (; e + 3 < s1; e += 4) {
            int2 m0 = __ldg(g_csr + e);
            int2 m1 = __ldg(g_csr + e + 1);
            int2 m2 = __ldg(g_csr + e + 2);
            int2 m3 = __ldg(g_csr + e + 3);
            float2 h0 = __half22float2(
                __ldg(reinterpret_cast<const __half2*>(g_h + m0.x * 64) + lane));
            float2 h1 = __half22float2(
                __ldg(reinterpret_cast<const __half2*>(g_h + m1.x * 64) + lane));
            float2 h2b = __half22float2(
                __ldg(reinterpret_cast<const __half2*>(g_h + m2.x * 64) + lane));
            float2 h3 = __half22float2(
                __ldg(reinterpret_cast<const __half2*>(g_h + m3.x * 64) + lane));
            float w0 = __int_as_float(m0.y);
            float w1 = __int_as_float(m1.y);
            float w2 = __int_as_float(m2.y);
            float w3 = __int_as_float(m3.y);
            acc.x += w0 * h0.x + w1 * h1.x + w2 * h2b.x + w3 * h3.x;
            acc.y += w0 * h0.y + w1 * h1.y + w2 * h2b.y + w3 * h3.y;
        }
        for (; e < s1; e++) {
            int2 ma = __ldg(g_csr + e);
            float wa = __int_as_float(ma.y);
            float2 ha = __half22float2(
                __ldg(reinterpret_cast<const __half2*>(g_h + ma.x * 64) + lane));
            acc.x += wa * ha.x;
            acc.y += wa * ha.y;
        }
        *reinterpret_cast<float2*>(g_agg + n * 64 + lane * 2) = acc;
    }

    atomicAdd(&s_stats[2 * lane],          acc.x);
    atomicAdd(&s_stats[2 * lane + 1],      acc.y);
    atomicAdd(&s_stats[64 + 2 * lane],     acc.x * acc.x);
    atomicAdd(&s_stats[64 + 2 * lane + 1], acc.y * acc.y);
    __syncthreads();
    if (tid < 128) atomicAdd(&g_stats[layer * 128 + tid], s_stats[tid]);
}

// ---------------- BN finalize + apply + residual relu (layer 1 only) ------------
__global__ void k_bn_apply(const float* __restrict__ gamma,
                           const float* __restrict__ beta, int layer) {
    __shared__ float sc[64], sf[64];
    int tid = threadIdx.x;
    if (tid < 64) {
        float mu  = g_stats[layer * 128 + tid] * (1.0f / NN);
        float var = g_stats[layer * 128 + 64 + tid] * (1.0f / NN) - mu * mu;
        float inv = rsqrtf(var + BN_EPS);
        float gm  = gamma[tid];
        sc[tid] = gm * inv;
        sf[tid] = beta[tid] - mu * inv * gm;
    }
    __syncthreads();
    int i = blockIdx.x * blockDim.x + tid;
    if (i < NN * 16) {
        int c0 = (i & 15) * 4;
        float4 v = reinterpret_cast<const float4*>(g_agg)[i];
        float4 x = reinterpret_cast<const float4*>(g_x)[i];
        x.x += fmaxf(v.x * sc[c0 + 0] + sf[c0 + 0], 0.f);
        x.y += fmaxf(v.y * sc[c0 + 1] + sf[c0 + 1], 0.f);
        x.z += fmaxf(v.z * sc[c0 + 2] + sf[c0 + 2], 0.f);
        x.w += fmaxf(v.w * sc[c0 + 3] + sf[c0 + 3], 0.f);
        reinterpret_cast<float4*>(g_x)[i] = x;
    }
}

// ---------------- link decoder ----------------
__global__ void k_decode(const int* __restrict__ pe, float* __restrict__ out) {
    int w = (blockIdx.x * blockDim.x + threadIdx.x) >> 5;
    int lane = threadIdx.x & 31;
    if (w >= EP) return;
    int a = __ldg(pe + 2 * w);
    int b = __ldg(pe + 2 * w + 1);
    float2 za = __ldg(reinterpret_cast<const float2*>(g_x + a * 64) + lane);
    float2 zb = __ldg(reinterpret_cast<const float2*>(g_x + b * 64) + lane);
    float s = za.x * zb.x + za.y * zb.y;
#pragma unroll
    for (int o = 16; o; o >>= 1) s += __shfl_xor_sync(0xffffffffu, s, o);
    if (lane == 0) out[w] = s;
}

// ---------------- launch: fork-join — CSR build || (proj -> conv0) ----------------
extern "C" void kernel_launch(void* const* d_in, const int* in_sizes, int n_in,
                              void* d_out, int out_size) {
    const int*   edge_index = (const int*)d_in[0];
    const int*   pred_edge  = (const int*)d_in[1];
    const float* id_emb     = (const float*)d_in[2];
    const float* n2v_emb    = (const float*)d_in[3];
    const float* proj_w     = (const float*)d_in[4];
    const float* proj_b     = (const float*)d_in[5];
    const float* conv_w     = (const float*)d_in[6];
    const float* conv_b     = (const float*)d_in[7];
    const float* bn_gamma   = (const float*)d_in[8];
    const float* bn_beta    = (const float*)d_in[9];
    float*       out        = (float*)d_out;

    static cudaStream_t s_aux = 0;
    static cudaEvent_t ev_fork = 0, ev_join = 0;
    if (!s_aux) {
        cudaStreamCreateWithFlags(&s_aux, cudaStreamNonBlocking);
        cudaEventCreateWithFlags(&ev_fork, cudaEventDisableTiming);
        cudaEventCreateWithFlags(&ev_join, cudaEventDisableTiming);
    }

    const int TB = 256;
    const int GBLK = (NN + 63) / 64;       // 64-row MMA tiles

    // fork: aux stream runs proj -> conv0 (touches only g_x/g_h)
    cudaEventRecord(ev_fork, 0);
    cudaStreamWaitEvent(s_aux, ev_fork, 0);
    k_proj<<<GBLK, TB, 0, s_aux>>>(id_emb, n2v_emb, proj_w, proj_b);
    k_conv<<<GBLK, TB, 0, s_aux>>>(conv_w);
    cudaEventRecord(ev_join, s_aux);

    // main stream: CSR build (touches only deg/dis/csr/stats)
    k_init      <<<(NN + TB - 1) / TB, TB>>>();
    k_deg_count <<<(EE / 2 + TB - 1) / TB, TB>>>(edge_index);
    k_scan_part <<<NB_SCAN, TB>>>();
    k_scan_write<<<NB_SCAN, TB>>>();
    k_csr_fill  <<<(EE / 2 + TB - 1) / TB, TB>>>(edge_index);

    // join: gather0 needs both CSR and h0
    cudaStreamWaitEvent(0, ev_join, 0);

    k_gather  <<<(NN * 32 + TB - 1) / TB, TB>>>(conv_b, 0);
    k_bn_conv1<<<GBLK, TB>>>(conv_w + HID * HID, bn_gamma, bn_beta);
    k_gather  <<<(NN * 32 + TB - 1) / TB, TB>>>(conv_b + HID, 1);
    k_bn_apply<<<(NN * 16 + TB - 1) / TB, TB>>>(bn_gamma + HID, bn_beta + HID, 1);

    k_decode<<<(EP * 32 + TB - 1) / TB, TB>>>(pred_edge, out);
}